// round 7
// baseline (speedup 1.0000x reference)
#include <cuda_runtime.h>
#include <cuda_bf16.h>
#include <math.h>

#define Bd 64
#define Td 256
#define Ed 256
#define Ud 1024
#define Gd 3072   // 3*Ud
#define NCTA_DIR 64
#define THREADS 256
#define NCHUNK 64          // 1024 / 16
#define USTRIDE 1032       // padded k-stride for U smem (conflict-free ldmatrix)
#define ASTRIDE 24         // padded k-stride for A stage smem (conflict-free ldmatrix)

// ---------------- device scratch (allocation-free rule) ----------------
__device__ float g_xe[Bd * Td * Ed];
__device__ float g_gx[2][(size_t)Bd * Td * Gd];          // x@W + b_in
__device__ float g_h[2][2][Bd][Ud];                      // [dir][parity][b][u] fp32
__device__ __nv_bfloat16 g_hbf[2][2][2][Bd][Ud];         // [dir][parity][hi/lo][b][u]
__device__ __nv_bfloat16 g_Ubf[2][2][Gd][Ud];            // [dir][hi/lo][n][k] (k-contig)
__device__ unsigned g_cnt[2];
__device__ unsigned g_gen[2];

// ---------------- helpers ----------------
__device__ __forceinline__ unsigned long long pack2(float lo, float hi) {
    unsigned long long r;
    asm("mov.b64 %0, {%1, %2};" : "=l"(r) : "f"(lo), "f"(hi));
    return r;
}
__device__ __forceinline__ void unpack2(unsigned long long v, float& lo, float& hi) {
    asm("mov.b64 {%0, %1}, %2;" : "=f"(lo), "=f"(hi) : "l"(v));
}
__device__ __forceinline__ void fma2(unsigned long long& acc,
                                     unsigned long long a, unsigned long long b) {
    asm("fma.rn.f32x2 %0, %1, %2, %0;" : "+l"(acc) : "l"(a), "l"(b));
}

#define MMA_BF16(C, A0, A1, A2, A3, B0, B1)                                   \
    asm volatile(                                                             \
        "mma.sync.aligned.m16n8k16.row.col.f32.bf16.bf16.f32 "                \
        "{%0,%1,%2,%3}, {%4,%5,%6,%7}, {%8,%9}, {%0,%1,%2,%3};"               \
        : "+f"(C[0]), "+f"(C[1]), "+f"(C[2]), "+f"(C[3])                      \
        : "r"(A0), "r"(A1), "r"(A2), "r"(A3), "r"(B0), "r"(B1))

__device__ __forceinline__ void ldsm_x4(unsigned& r0, unsigned& r1,
                                        unsigned& r2, unsigned& r3,
                                        const void* p) {
    unsigned a = (unsigned)__cvta_generic_to_shared(p);
    asm volatile("ldmatrix.sync.aligned.m8n8.x4.shared.b16 {%0,%1,%2,%3}, [%4];"
                 : "=r"(r0), "=r"(r1), "=r"(r2), "=r"(r3) : "r"(a));
}
__device__ __forceinline__ void ldsm_x2(unsigned& r0, unsigned& r1, const void* p) {
    unsigned a = (unsigned)__cvta_generic_to_shared(p);
    asm volatile("ldmatrix.sync.aligned.m8n8.x2.shared.b16 {%0,%1}, [%2];"
                 : "=r"(r0), "=r"(r1) : "r"(a));
}

__device__ __forceinline__ float sigf(float a) {
    return 1.f / (1.f + __expf(-a));
}

// ---------------------------------------------------------------------------
// 1) Embedding gather
// ---------------------------------------------------------------------------
__global__ void k_embed(const int* __restrict__ x, const float* __restrict__ emb) {
    int bt = blockIdx.x;
    int tok = x[bt];
    g_xe[bt * Ed + threadIdx.x] = emb[tok * Ed + threadIdx.x];
}

// ---------------------------------------------------------------------------
// 2) Init hidden: fp32 double buffers (parity 0) + bf16 hi/lo split
// ---------------------------------------------------------------------------
__global__ void k_init(const float* __restrict__ hidden) {
    int i = blockIdx.x * blockDim.x + threadIdx.x;   // 65536
    float v = hidden[i];
    int b = i >> 10, k = i & 1023;
    g_h[0][0][b][k] = v;
    g_h[1][0][b][k] = v;
    __nv_bfloat16 hi = __float2bfloat16(v);
    __nv_bfloat16 lo = __float2bfloat16(v - __bfloat162float(hi));
    g_hbf[0][0][0][b][k] = hi; g_hbf[0][0][1][b][k] = lo;
    g_hbf[1][0][0][b][k] = hi; g_hbf[1][0][1][b][k] = lo;
}

// ---------------------------------------------------------------------------
// 3) U split+transpose: g_Ubf[dir][hi/lo][n][k] from U[k][n] (32x32 smem tiles)
// ---------------------------------------------------------------------------
__global__ void k_usplit(const float* __restrict__ Uf, const float* __restrict__ Ub) {
    __shared__ float tile[32][33];
    int dir = blockIdx.z;
    const float* U = dir ? Ub : Uf;
    int n0 = blockIdx.x * 32, k0 = blockIdx.y * 32;

    for (int i = threadIdx.y; i < 32; i += 8)
        tile[i][threadIdx.x] = U[(size_t)(k0 + i) * Gd + n0 + threadIdx.x];
    __syncthreads();
    for (int i = threadIdx.y; i < 32; i += 8) {
        float u = tile[threadIdx.x][i];              // (k = k0+tx, n = n0+i)
        __nv_bfloat16 hi = __float2bfloat16(u);
        __nv_bfloat16 lo = __float2bfloat16(u - __bfloat162float(hi));
        g_Ubf[dir][0][n0 + i][k0 + threadIdx.x] = hi;
        g_Ubf[dir][1][n0 + i][k0 + threadIdx.x] = lo;
    }
}

// ---------------------------------------------------------------------------
// 4) Input GEMM (f32x2): gx = xe (16384x256) @ W (256x3072) + b_in
// ---------------------------------------------------------------------------
__global__ void k_ingemm(const float* __restrict__ Wf, const float* __restrict__ Wb,
                         const float* __restrict__ bf, const float* __restrict__ bb) {
    int dir = blockIdx.z;
    const float* W    = dir ? Wb : Wf;
    const float* bias = dir ? bb : bf;
    float* C = g_gx[dir];

    int n0 = blockIdx.x * 64;
    int m0 = blockIdx.y * 64;

    __shared__ float As_[32][65];
    __shared__ float Bs_[32][64];

    int tid = threadIdx.x;
    int tx = tid & 15, ty = tid >> 4;

    unsigned long long acc[4][2] = {};

    for (int k0 = 0; k0 < Ed; k0 += 32) {
        #pragma unroll
        for (int i = 0; i < 8; i++) {
            int idx = tid + i * 256;
            int m = idx >> 5, k = idx & 31;
            As_[k][m] = g_xe[(m0 + m) * Ed + k0 + k];
        }
        #pragma unroll
        for (int i = 0; i < 8; i++) {
            int idx = tid + i * 256;
            int k = idx >> 6, n = idx & 63;
            Bs_[k][n] = W[(size_t)(k0 + k) * Gd + n0 + n];
        }
        __syncthreads();

        #pragma unroll
        for (int k = 0; k < 32; k++) {
            unsigned long long b01 =
                *reinterpret_cast<const unsigned long long*>(&Bs_[k][tx * 4]);
            unsigned long long b23 =
                *reinterpret_cast<const unsigned long long*>(&Bs_[k][tx * 4 + 2]);
            #pragma unroll
            for (int i = 0; i < 4; i++) {
                float a = As_[k][ty * 4 + i];
                unsigned long long ap = pack2(a, a);
                fma2(acc[i][0], ap, b01);
                fma2(acc[i][1], ap, b23);
            }
        }
        __syncthreads();
    }

    #pragma unroll
    for (int i = 0; i < 4; i++) {
        float v0, v1, v2, v3;
        unpack2(acc[i][0], v0, v1);
        unpack2(acc[i][1], v2, v3);
        int n = n0 + tx * 4;
        size_t row = (size_t)(m0 + ty * 4 + i) * Gd;
        C[row + n + 0] = v0 + bias[n + 0];
        C[row + n + 1] = v1 + bias[n + 1];
        C[row + n + 2] = v2 + bias[n + 2];
        C[row + n + 3] = v3 + bias[n + 3];
    }
}

// ---------------------------------------------------------------------------
// 5) Persistent recurrence, bf16 3-split tensor-core step GEMM with a
//    3-deep register prefetch pipeline decoupling LDG from STS:
//      chunk i:  STS regs(chunk i+1); LDG chunk i+3 -> regs;
//                ldmatrix frags(chunk i); 9x mma; __syncthreads
//    so the global->smem path never exposes L2 latency.
// ---------------------------------------------------------------------------
__global__ void __launch_bounds__(THREADS, 1)
k_recur(const int* __restrict__ x,
        const float* __restrict__ brf, const float* __restrict__ brb,
        float* __restrict__ out) {
    extern __shared__ unsigned char smraw[];
    __nv_bfloat16* Us = (__nv_bfloat16*)smraw;                 // [2][48][USTRIDE]
    __nv_bfloat16* Ast = (__nv_bfloat16*)(smraw + 2 * 48 * USTRIDE * 2); // [2buf][2][64][ASTRIDE]

    int bx = blockIdx.x;
    int dir = bx >> 6;
    int c0 = (bx & 63) * 16;
    const float* brec = dir ? brb : brf;
    const float* gx = g_gx[dir];
    int tid = threadIdx.x;
    int wid = tid >> 5, lane = tid & 31;
    int mt = wid & 3, nh = wid >> 2;
    int g = lane >> 2, tg = lane & 3;

    // load U slice (bf16 hi/lo) once
    for (int idx = tid; idx < 2 * 48 * 1024; idx += THREADS) {
        int s = idx / 49152;
        int rem = idx - s * 49152;
        int j = rem >> 10;
        int k = rem & 1023;
        int gate = j >> 4, c = j & 15;
        Us[(s * 48 + j) * USTRIDE + k] = g_Ubf[dir][s][gate * 1024 + c0 + c][k];
    }

    // per-thread output coordinates
    int rl = mt * 16 + g, rh = rl + 8;           // batch rows
    int cb = c0 + nh * 8 + 2 * tg;               // h-col pair base (even)

    // recurrent biases (once)
    float2 Bz = *(const float2*)&brec[cb];
    float2 Br = *(const float2*)&brec[Ud + cb];
    float2 Bh = *(const float2*)&brec[2 * Ud + cb];

    // A staging coords (cooperative, coalesced)
    int sr = tid >> 2;                // 0..63 row
    int sq = (tid & 3) * 4;           // k quad within chunk

    // ldmatrix source addresses (element offsets, fixed per thread)
    int a_row = mt * 16 + (lane & 15);
    int a_col = (lane >> 4) * 8;
    int b_row_l = lane & 7;           // within gate tile
    int b_col_l = ((lane >> 3) & 1) * 8;

    unsigned* cnt = &g_cnt[dir];
    unsigned* gen = &g_gen[dir];

    __syncthreads();

    for (int s = 0; s < Td; s++) {
        int t = dir ? (Td - 1 - s) : s;
        int par = s & 1;

        // ---- prefetch epilogue operands (independent of GEMM) ----
        size_t gl = (size_t)(rl * Td + t) * Gd + cb;
        size_t gh = (size_t)(rh * Td + t) * Gd + cb;
        float2 gz_l = __ldcg((const float2*)&gx[gl]);
        float2 gr_l = __ldcg((const float2*)&gx[gl + Ud]);
        float2 gh_l = __ldcg((const float2*)&gx[gl + 2 * Ud]);
        float2 gz_h = __ldcg((const float2*)&gx[gh]);
        float2 gr_h = __ldcg((const float2*)&gx[gh + Ud]);
        float2 gh_h = __ldcg((const float2*)&gx[gh + 2 * Ud]);
        float2 ho_l = __ldcg((const float2*)&g_h[dir][par][rl][cb]);
        float2 ho_h = __ldcg((const float2*)&g_h[dir][par][rh][cb]);
        int xl = __ldcg(&x[rl * Td + t]);
        int xh = __ldcg(&x[rh * Td + t]);

        float C0[4] = {0.f, 0.f, 0.f, 0.f};   // z tile
        float C1[4] = {0.f, 0.f, 0.f, 0.f};   // r tile
        float C2[4] = {0.f, 0.f, 0.f, 0.f};   // h~ tile

        const __nv_bfloat16* hbf_hi = &g_hbf[dir][par][0][0][0];
        const __nv_bfloat16* hbf_lo = &g_hbf[dir][par][1][0][0];

        // ---- register prefetch pipeline: preload chunks 0,1,2 ----
        uint2 Rhi[3], Rlo[3];
        #pragma unroll
        for (int j = 0; j < 3; j++) {
            Rhi[j] = __ldcg((const uint2*)&hbf_hi[sr * Ud + j * 16 + sq]);
            Rlo[j] = __ldcg((const uint2*)&hbf_lo[sr * Ud + j * 16 + sq]);
        }
        // STS chunk 0 (slot 0) into buf 0
        *(uint2*)&Ast[((0 * 2 + 0) * 64 + sr) * ASTRIDE + sq] = Rhi[0];
        *(uint2*)&Ast[((0 * 2 + 1) * 64 + sr) * ASTRIDE + sq] = Rlo[0];
        __syncthreads();

        int sts_slot = 1, ldg_slot = 0;
        for (int ch = 0; ch < NCHUNK; ch++) {
            int buf = ch & 1;
            // store chunk ch+1 (arrived long ago) into the other buffer
            if (ch + 1 < NCHUNK) {
                int bn = buf ^ 1;
                *(uint2*)&Ast[((bn * 2 + 0) * 64 + sr) * ASTRIDE + sq] = Rhi[sts_slot];
                *(uint2*)&Ast[((bn * 2 + 1) * 64 + sr) * ASTRIDE + sq] = Rlo[sts_slot];
                sts_slot = (sts_slot == 2) ? 0 : sts_slot + 1;
            }
            // issue load for chunk ch+3 into the slot just freed
            if (ch + 3 < NCHUNK) {
                int k0n = (ch + 3) * 16;
                Rhi[ldg_slot] = __ldcg((const uint2*)&hbf_hi[sr * Ud + k0n + sq]);
                Rlo[ldg_slot] = __ldcg((const uint2*)&hbf_lo[sr * Ud + k0n + sq]);
                ldg_slot = (ldg_slot == 2) ? 0 : ldg_slot + 1;
            }

            // A fragments via ldmatrix (hi, lo)
            const __nv_bfloat16* ah = &Ast[(buf * 2 + 0) * 64 * ASTRIDE];
            const __nv_bfloat16* al = &Ast[(buf * 2 + 1) * 64 * ASTRIDE];
            unsigned ahi0, ahi1, ahi2, ahi3, alo0, alo1, alo2, alo3;
            ldsm_x4(ahi0, ahi1, ahi2, ahi3, &ah[a_row * ASTRIDE + a_col]);
            ldsm_x4(alo0, alo1, alo2, alo3, &al[a_row * ASTRIDE + a_col]);

            int k0 = ch * 16;
            #pragma unroll
            for (int gt = 0; gt < 3; gt++) {
                int nt = gt * 2 + nh;                 // ntile
                unsigned bhi0, bhi1, blo0, blo1;
                ldsm_x2(bhi0, bhi1,
                        &Us[(0 * 48 + nt * 8 + b_row_l) * USTRIDE + k0 + b_col_l]);
                ldsm_x2(blo0, blo1,
                        &Us[(1 * 48 + nt * 8 + b_row_l) * USTRIDE + k0 + b_col_l]);
                float* Cp = (gt == 0) ? C0 : (gt == 1) ? C1 : C2;
                MMA_BF16(Cp, ahi0, ahi1, ahi2, ahi3, bhi0, bhi1);
                MMA_BF16(Cp, ahi0, ahi1, ahi2, ahi3, blo0, blo1);
                MMA_BF16(Cp, alo0, alo1, alo2, alo3, bhi0, bhi1);
            }
            __syncthreads();
        }

        // ---- epilogue: gates for 2x2 outputs ----
        float hn[4];
        {
            float z0 = sigf(gz_l.x + C0[0] + Bz.x);
            float z1 = sigf(gz_l.y + C0[1] + Bz.y);
            float r0 = sigf(gr_l.x + C1[0] + Br.x);
            float r1 = sigf(gr_l.y + C1[1] + Br.y);
            float t0 = tanhf(gh_l.x + r0 * (C2[0] + Bh.x));
            float t1 = tanhf(gh_l.y + r1 * (C2[1] + Bh.y));
            hn[0] = z0 * ho_l.x + (1.f - z0) * t0;
            hn[1] = z1 * ho_l.y + (1.f - z1) * t1;
            if (xl == 0) { hn[0] = ho_l.x; hn[1] = ho_l.y; }

            float z2 = sigf(gz_h.x + C0[2] + Bz.x);
            float z3 = sigf(gz_h.y + C0[3] + Bz.y);
            float r2 = sigf(gr_h.x + C1[2] + Br.x);
            float r3 = sigf(gr_h.y + C1[3] + Br.y);
            float t2 = tanhf(gh_h.x + r2 * (C2[2] + Bh.x));
            float t3 = tanhf(gh_h.y + r3 * (C2[3] + Bh.y));
            hn[2] = z2 * ho_h.x + (1.f - z2) * t2;
            hn[3] = z3 * ho_h.y + (1.f - z3) * t3;
            if (xh == 0) { hn[2] = ho_h.x; hn[3] = ho_h.y; }
        }

        int pn = par ^ 1;
        *(float2*)&g_h[dir][pn][rl][cb] = make_float2(hn[0], hn[1]);
        *(float2*)&g_h[dir][pn][rh][cb] = make_float2(hn[2], hn[3]);

        #pragma unroll
        for (int rr = 0; rr < 2; rr++) {
            int b = rr ? rh : rl;
            float v0 = hn[rr * 2], v1 = hn[rr * 2 + 1];
            __nv_bfloat16 h0 = __float2bfloat16(v0);
            __nv_bfloat16 h1 = __float2bfloat16(v1);
            __nv_bfloat16 l0 = __float2bfloat16(v0 - __bfloat162float(h0));
            __nv_bfloat16 l1 = __float2bfloat16(v1 - __bfloat162float(h1));
            __nv_bfloat162 hp; hp.x = h0; hp.y = h1;
            __nv_bfloat162 lp; lp.x = l0; lp.y = l1;
            *(__nv_bfloat162*)&g_hbf[dir][pn][0][b][cb] = hp;
            *(__nv_bfloat162*)&g_hbf[dir][pn][1][b][cb] = lp;
            *(float2*)&out[(size_t)(b * Td + t) * (2 * Ud) + dir * Ud + cb] =
                make_float2(v0, v1);
        }

        // ---- per-direction grid barrier ----
        __syncthreads();
        if (tid == 0) {
            unsigned my;
            asm volatile("ld.acquire.gpu.u32 %0, [%1];" : "=r"(my) : "l"(gen));
            __threadfence();
            unsigned prev = atomicAdd(cnt, 1u);
            if (prev == NCTA_DIR - 1) {
                atomicExch(cnt, 0u);
                __threadfence();
                atomicAdd(gen, 1u);
            } else {
                unsigned cg;
                do {
                    __nanosleep(64);
                    asm volatile("ld.acquire.gpu.u32 %0, [%1];" : "=r"(cg) : "l"(gen));
                } while (cg == my);
            }
        }
        __syncthreads();
    }
}

// ---------------------------------------------------------------------------
// 6) Projection: state = tanh([hf|hb] @ Wp + bp)  (final h at parity 0)
// ---------------------------------------------------------------------------
__global__ void k_proj(const float* __restrict__ Wp, const float* __restrict__ bp,
                       float* __restrict__ out) {
    float* state = out + (size_t)Bd * Td * 2 * Ud;
    int b = blockIdx.x;

    __shared__ float cat[2 * Ud];
    for (int i = threadIdx.x; i < Ud; i += blockDim.x) {
        cat[i]      = g_h[0][0][b][i];
        cat[Ud + i] = g_h[1][0][b][i];
    }
    __syncthreads();

    for (int u = threadIdx.x; u < Ud; u += 256) {
        float acc = bp[u];
        for (int k = 0; k < 2 * Ud; k++)
            acc += cat[k] * Wp[(size_t)k * Ud + u];
        state[b * Ud + u] = tanhf(acc);
    }
}

// ---------------------------------------------------------------------------
extern "C" void kernel_launch(void* const* d_in, const int* in_sizes, int n_in,
                              void* d_out, int out_size) {
    const int*   x      = (const int*)d_in[0];
    const float* hidden = (const float*)d_in[1];
    const float* emb    = (const float*)d_in[2];
    const float* Wf     = (const float*)d_in[3];
    const float* Uf     = (const float*)d_in[4];
    const float* bf_in  = (const float*)d_in[5];
    const float* bf_rec = (const float*)d_in[6];
    const float* Wb     = (const float*)d_in[7];
    const float* Ub     = (const float*)d_in[8];
    const float* bb_in  = (const float*)d_in[9];
    const float* bb_rec = (const float*)d_in[10];
    const float* Wp     = (const float*)d_in[11];
    const float* bp     = (const float*)d_in[12];
    float* out = (float*)d_out;

    const int smem_bytes = (2 * 48 * USTRIDE + 2 * 2 * 64 * ASTRIDE) * 2; // 210432
    cudaFuncSetAttribute(k_recur, cudaFuncAttributeMaxDynamicSharedMemorySize,
                         smem_bytes);

    k_embed<<<Bd * Td, 256>>>(x, emb);
    k_init<<<(Bd * Ud) / 256, 256>>>(hidden);

    dim3 gu(Gd / 32, Ud / 32, 2);
    k_usplit<<<gu, dim3(32, 8)>>>(Uf, Ub);

    dim3 gi(Gd / 64, (Bd * Td) / 64, 2);
    k_ingemm<<<gi, 256>>>(Wf, Wb, bf_in, bb_in);

    k_recur<<<2 * NCTA_DIR, THREADS, smem_bytes>>>(x, bf_rec, bb_rec, out);

    k_proj<<<Bd, 256>>>(Wp, bp, out);
}

// round 8
// speedup vs baseline: 2.2578x; 2.2578x over previous
#include <cuda_runtime.h>
#include <cuda_bf16.h>
#include <math.h>

#define Bd 64
#define Td 256
#define Ed 256
#define Ud 1024
#define Gd 3072   // 3*Ud
#define NCTA_DIR 64
#define THREADS 256
#define NCHUNK 64          // 1024 / 16
#define USTRIDE 1032       // padded k-stride for U smem (conflict-free ldmatrix)

// ---------------- device scratch (allocation-free rule) ----------------
__device__ float g_xe[Bd * Td * Ed];
__device__ float g_gx[2][(size_t)Bd * Td * Gd];          // x@W + b_in
__device__ float g_h[2][2][Bd][Ud];                      // [dir][parity][b][u] fp32
// h in mma-A-fragment layout: [dir][parity][hi/lo][chunk][mtile][lane] -> 4 regs
__device__ uint4 g_hf[2][2][2][NCHUNK][4][32];
__device__ __nv_bfloat16 g_Ubf[2][2][Gd][Ud];            // [dir][hi/lo][n][k] (k-contig)
__device__ unsigned g_cnt[2];
__device__ unsigned g_gen[2];

// ---------------- helpers ----------------
__device__ __forceinline__ unsigned long long pack2(float lo, float hi) {
    unsigned long long r;
    asm("mov.b64 %0, {%1, %2};" : "=l"(r) : "f"(lo), "f"(hi));
    return r;
}
__device__ __forceinline__ void unpack2(unsigned long long v, float& lo, float& hi) {
    asm("mov.b64 {%0, %1}, %2;" : "=f"(lo), "=f"(hi) : "l"(v));
}
__device__ __forceinline__ void fma2(unsigned long long& acc,
                                     unsigned long long a, unsigned long long b) {
    asm("fma.rn.f32x2 %0, %1, %2, %0;" : "+l"(acc) : "l"(a), "l"(b));
}

#define MMA_BF16(C, A0, A1, A2, A3, B0, B1)                                   \
    asm volatile(                                                             \
        "mma.sync.aligned.m16n8k16.row.col.f32.bf16.bf16.f32 "                \
        "{%0,%1,%2,%3}, {%4,%5,%6,%7}, {%8,%9}, {%0,%1,%2,%3};"               \
        : "+f"(C[0]), "+f"(C[1]), "+f"(C[2]), "+f"(C[3])                      \
        : "r"(A0), "r"(A1), "r"(A2), "r"(A3), "r"(B0), "r"(B1))

__device__ __forceinline__ void ldsm_x2(unsigned& r0, unsigned& r1, const void* p) {
    unsigned a = (unsigned)__cvta_generic_to_shared(p);
    asm volatile("ldmatrix.sync.aligned.m8n8.x2.shared.b16 {%0,%1}, [%2];"
                 : "=r"(r0), "=r"(r1) : "r"(a));
}

__device__ __forceinline__ float sigf(float a) {
    return 1.f / (1.f + __expf(-a));
}
__device__ __forceinline__ unsigned bf2u(float a, float b) {
    __nv_bfloat162 t;
    t.x = __float2bfloat16(a);
    t.y = __float2bfloat16(b);
    return *reinterpret_cast<unsigned*>(&t);
}

// ---------------------------------------------------------------------------
// 1) Embedding gather
// ---------------------------------------------------------------------------
__global__ void k_embed(const int* __restrict__ x, const float* __restrict__ emb) {
    int bt = blockIdx.x;
    int tok = x[bt];
    g_xe[bt * Ed + threadIdx.x] = emb[tok * Ed + threadIdx.x];
}

// ---------------------------------------------------------------------------
// 2) Init hidden: fp32 double buffers (parity 0) + fragment-layout hi/lo
// ---------------------------------------------------------------------------
__global__ void k_init(const float* __restrict__ hidden) {
    int i = blockIdx.x * blockDim.x + threadIdx.x;   // 65536
    float v = hidden[i];
    int b = i >> 10, k = i & 1023;
    g_h[0][0][b][k] = v;
    g_h[1][0][b][k] = v;

    __nv_bfloat16 hi = __float2bfloat16(v);
    __nv_bfloat16 lo = __float2bfloat16(v - __bfloat162float(hi));

    int ch = k >> 4, cc = k & 15;
    int mtp = b >> 4, rt = b & 15;
    int gp = rt & 7, hir = rt >> 3;
    int tgp = (cc >> 1) & 3, chh = cc >> 3, pr = cc & 1;
    int lane = gp * 4 + tgp;
    int aidx = hir + 2 * chh;
    #pragma unroll
    for (int d = 0; d < 2; d++) {
        ((__nv_bfloat16*)&g_hf[d][0][0][ch][mtp][lane])[aidx * 2 + pr] = hi;
        ((__nv_bfloat16*)&g_hf[d][0][1][ch][mtp][lane])[aidx * 2 + pr] = lo;
    }
}

// ---------------------------------------------------------------------------
// 3) U split+transpose: g_Ubf[dir][hi/lo][n][k] from U[k][n] (32x32 smem tiles)
// ---------------------------------------------------------------------------
__global__ void k_usplit(const float* __restrict__ Uf, const float* __restrict__ Ub) {
    __shared__ float tile[32][33];
    int dir = blockIdx.z;
    const float* U = dir ? Ub : Uf;
    int n0 = blockIdx.x * 32, k0 = blockIdx.y * 32;

    for (int i = threadIdx.y; i < 32; i += 8)
        tile[i][threadIdx.x] = U[(size_t)(k0 + i) * Gd + n0 + threadIdx.x];
    __syncthreads();
    for (int i = threadIdx.y; i < 32; i += 8) {
        float u = tile[threadIdx.x][i];              // (k = k0+tx, n = n0+i)
        __nv_bfloat16 hi = __float2bfloat16(u);
        __nv_bfloat16 lo = __float2bfloat16(u - __bfloat162float(hi));
        g_Ubf[dir][0][n0 + i][k0 + threadIdx.x] = hi;
        g_Ubf[dir][1][n0 + i][k0 + threadIdx.x] = lo;
    }
}

// ---------------------------------------------------------------------------
// 4) Input GEMM (f32x2): gx = xe (16384x256) @ W (256x3072) + b_in
// ---------------------------------------------------------------------------
__global__ void k_ingemm(const float* __restrict__ Wf, const float* __restrict__ Wb,
                         const float* __restrict__ bf, const float* __restrict__ bb) {
    int dir = blockIdx.z;
    const float* W    = dir ? Wb : Wf;
    const float* bias = dir ? bb : bf;
    float* C = g_gx[dir];

    int n0 = blockIdx.x * 64;
    int m0 = blockIdx.y * 64;

    __shared__ float As_[32][65];
    __shared__ float Bs_[32][64];

    int tid = threadIdx.x;
    int tx = tid & 15, ty = tid >> 4;

    unsigned long long acc[4][2] = {};

    for (int k0 = 0; k0 < Ed; k0 += 32) {
        #pragma unroll
        for (int i = 0; i < 8; i++) {
            int idx = tid + i * 256;
            int m = idx >> 5, k = idx & 31;
            As_[k][m] = g_xe[(m0 + m) * Ed + k0 + k];
        }
        #pragma unroll
        for (int i = 0; i < 8; i++) {
            int idx = tid + i * 256;
            int k = idx >> 6, n = idx & 63;
            Bs_[k][n] = W[(size_t)(k0 + k) * Gd + n0 + n];
        }
        __syncthreads();

        #pragma unroll
        for (int k = 0; k < 32; k++) {
            unsigned long long b01 =
                *reinterpret_cast<const unsigned long long*>(&Bs_[k][tx * 4]);
            unsigned long long b23 =
                *reinterpret_cast<const unsigned long long*>(&Bs_[k][tx * 4 + 2]);
            #pragma unroll
            for (int i = 0; i < 4; i++) {
                float a = As_[k][ty * 4 + i];
                unsigned long long ap = pack2(a, a);
                fma2(acc[i][0], ap, b01);
                fma2(acc[i][1], ap, b23);
            }
        }
        __syncthreads();
    }

    #pragma unroll
    for (int i = 0; i < 4; i++) {
        float v0, v1, v2, v3;
        unpack2(acc[i][0], v0, v1);
        unpack2(acc[i][1], v2, v3);
        int n = n0 + tx * 4;
        size_t row = (size_t)(m0 + ty * 4 + i) * Gd;
        C[row + n + 0] = v0 + bias[n + 0];
        C[row + n + 1] = v1 + bias[n + 1];
        C[row + n + 2] = v2 + bias[n + 2];
        C[row + n + 3] = v3 + bias[n + 3];
    }
}

// ---------------------------------------------------------------------------
// 5) Persistent recurrence: sync-free chunk loop.
//    h lives in gmem in mma-A-fragment layout (hi/lo). Per chunk per warp:
//    2x LDG.128 (A frags, L2-hot, prefetched 4 deep) + 6x ldmatrix (B from
//    resident smem) + 9x mma. No __syncthreads, no staging smem.
//    Epilogue writes next h directly in fragment layout (this CTA owns
//    exactly chunk bx&63). Grid barrier per step per direction.
// ---------------------------------------------------------------------------
__global__ void __launch_bounds__(THREADS, 1)
k_recur(const int* __restrict__ x,
        const float* __restrict__ brf, const float* __restrict__ brb,
        float* __restrict__ out) {
    extern __shared__ unsigned char smraw[];
    __nv_bfloat16* Us = (__nv_bfloat16*)smraw;                 // [2][48][USTRIDE]

    int bx = blockIdx.x;
    int dir = bx >> 6;
    int c0 = (bx & 63) * 16;
    int ch_own = bx & 63;
    const float* brec = dir ? brb : brf;
    const float* gx = g_gx[dir];
    int tid = threadIdx.x;
    int wid = tid >> 5, lane = tid & 31;
    int mt = wid & 3, nh = wid >> 2;
    int g = lane >> 2, tg = lane & 3;

    // load U slice (bf16 hi/lo) once
    for (int idx = tid; idx < 2 * 48 * 1024; idx += THREADS) {
        int s = idx / 49152;
        int rem = idx - s * 49152;
        int j = rem >> 10;
        int k = rem & 1023;
        int gate = j >> 4, c = j & 15;
        Us[(s * 48 + j) * USTRIDE + k] = g_Ubf[dir][s][gate * 1024 + c0 + c][k];
    }

    // per-thread output coordinates
    int rl = mt * 16 + g, rh = rl + 8;           // batch rows
    int cb = c0 + nh * 8 + 2 * tg;               // h-col pair base (even)

    float2 Bz = *(const float2*)&brec[cb];
    float2 Br = *(const float2*)&brec[Ud + cb];
    float2 Bh = *(const float2*)&brec[2 * Ud + cb];

    // B ldmatrix source coords
    int b_row_l = lane & 7;
    int b_col_l = ((lane >> 3) & 1) * 8;

    unsigned* cnt = &g_cnt[dir];
    unsigned* gen = &g_gen[dir];

    __syncthreads();

    for (int s = 0; s < Td; s++) {
        int t = dir ? (Td - 1 - s) : s;
        int par = s & 1;

        // ---- prefetch epilogue operands (independent of GEMM) ----
        size_t gl = (size_t)(rl * Td + t) * Gd + cb;
        size_t gh = (size_t)(rh * Td + t) * Gd + cb;
        float2 gz_l = __ldcg((const float2*)&gx[gl]);
        float2 gr_l = __ldcg((const float2*)&gx[gl + Ud]);
        float2 gh_l = __ldcg((const float2*)&gx[gl + 2 * Ud]);
        float2 gz_h = __ldcg((const float2*)&gx[gh]);
        float2 gr_h = __ldcg((const float2*)&gx[gh + Ud]);
        float2 gh_h = __ldcg((const float2*)&gx[gh + 2 * Ud]);
        float2 ho_l = __ldcg((const float2*)&g_h[dir][par][rl][cb]);
        float2 ho_h = __ldcg((const float2*)&g_h[dir][par][rh][cb]);
        int xl = __ldcg(&x[rl * Td + t]);
        int xh = __ldcg(&x[rh * Td + t]);

        float C0[4] = {0.f, 0.f, 0.f, 0.f};   // z tile
        float C1[4] = {0.f, 0.f, 0.f, 0.f};   // r tile
        float C2[4] = {0.f, 0.f, 0.f, 0.f};   // h~ tile

        // A-fragment base pointers for this warp (stride 128 uint4 per chunk)
        const uint4* hfA = &g_hf[dir][par][0][0][mt][lane];
        const uint4* hfL = &g_hf[dir][par][1][0][mt][lane];

        // 4-deep register prefetch of A fragments
        uint4 PA[4], PL[4];
        #pragma unroll
        for (int j = 0; j < 4; j++) {
            PA[j] = __ldcg(hfA + j * 128);
            PL[j] = __ldcg(hfL + j * 128);
        }

        #pragma unroll 4
        for (int ch = 0; ch < NCHUNK; ch++) {
            int sl = ch & 3;
            uint4 Ah = PA[sl];
            uint4 Al = PL[sl];
            if (ch + 4 < NCHUNK) {
                PA[sl] = __ldcg(hfA + (ch + 4) * 128);
                PL[sl] = __ldcg(hfL + (ch + 4) * 128);
            }

            int k0 = ch * 16;
            #pragma unroll
            for (int gt = 0; gt < 3; gt++) {
                int nt = gt * 2 + nh;                 // ntile
                unsigned bhi0, bhi1, blo0, blo1;
                ldsm_x2(bhi0, bhi1,
                        &Us[(0 * 48 + nt * 8 + b_row_l) * USTRIDE + k0 + b_col_l]);
                ldsm_x2(blo0, blo1,
                        &Us[(1 * 48 + nt * 8 + b_row_l) * USTRIDE + k0 + b_col_l]);
                float* Cp = (gt == 0) ? C0 : (gt == 1) ? C1 : C2;
                MMA_BF16(Cp, Ah.x, Ah.y, Ah.z, Ah.w, bhi0, bhi1);
                MMA_BF16(Cp, Ah.x, Ah.y, Ah.z, Ah.w, blo0, blo1);
                MMA_BF16(Cp, Al.x, Al.y, Al.z, Al.w, bhi0, bhi1);
            }
        }

        // ---- epilogue: gates for 2x2 outputs ----
        float hn[4];
        {
            float z0 = sigf(gz_l.x + C0[0] + Bz.x);
            float z1 = sigf(gz_l.y + C0[1] + Bz.y);
            float r0 = sigf(gr_l.x + C1[0] + Br.x);
            float r1 = sigf(gr_l.y + C1[1] + Br.y);
            float t0 = tanhf(gh_l.x + r0 * (C2[0] + Bh.x));
            float t1 = tanhf(gh_l.y + r1 * (C2[1] + Bh.y));
            hn[0] = z0 * ho_l.x + (1.f - z0) * t0;
            hn[1] = z1 * ho_l.y + (1.f - z1) * t1;
            if (xl == 0) { hn[0] = ho_l.x; hn[1] = ho_l.y; }

            float z2 = sigf(gz_h.x + C0[2] + Bz.x);
            float z3 = sigf(gz_h.y + C0[3] + Bz.y);
            float r2 = sigf(gr_h.x + C1[2] + Br.x);
            float r3 = sigf(gr_h.y + C1[3] + Br.y);
            float t2 = tanhf(gh_h.x + r2 * (C2[2] + Bh.x));
            float t3 = tanhf(gh_h.y + r3 * (C2[3] + Bh.y));
            hn[2] = z2 * ho_h.x + (1.f - z2) * t2;
            hn[3] = z3 * ho_h.y + (1.f - z3) * t3;
            if (xh == 0) { hn[2] = ho_h.x; hn[3] = ho_h.y; }
        }

        int pn = par ^ 1;
        *(float2*)&g_h[dir][pn][rl][cb] = make_float2(hn[0], hn[1]);
        *(float2*)&g_h[dir][pn][rh][cb] = make_float2(hn[2], hn[3]);

        // write next-step A fragments (hi/lo) for this CTA's chunk
        {
            float f0 = hn[0], f1 = hn[1], f2 = hn[2], f3 = hn[3];
            __nv_bfloat16 h0 = __float2bfloat16(f0);
            __nv_bfloat16 h1 = __float2bfloat16(f1);
            __nv_bfloat16 h2 = __float2bfloat16(f2);
            __nv_bfloat16 h3 = __float2bfloat16(f3);
            uint2 vhi, vlo;
            {
                __nv_bfloat162 p0; p0.x = h0; p0.y = h1;
                __nv_bfloat162 p1; p1.x = h2; p1.y = h3;
                vhi.x = *reinterpret_cast<unsigned*>(&p0);
                vhi.y = *reinterpret_cast<unsigned*>(&p1);
            }
            vlo.x = bf2u(f0 - __bfloat162float(h0), f1 - __bfloat162float(h1));
            vlo.y = bf2u(f2 - __bfloat162float(h2), f3 - __bfloat162float(h3));

            unsigned* fp_hi = (unsigned*)&g_hf[dir][pn][0][ch_own][mt][lane];
            unsigned* fp_lo = (unsigned*)&g_hf[dir][pn][1][ch_own][mt][lane];
            *(uint2*)(fp_hi + 2 * nh) = vhi;
            *(uint2*)(fp_lo + 2 * nh) = vlo;
        }

        #pragma unroll
        for (int rr = 0; rr < 2; rr++) {
            int b = rr ? rh : rl;
            *(float2*)&out[(size_t)(b * Td + t) * (2 * Ud) + dir * Ud + cb] =
                make_float2(hn[rr * 2], hn[rr * 2 + 1]);
        }

        // ---- per-direction grid barrier ----
        __syncthreads();
        if (tid == 0) {
            unsigned my;
            asm volatile("ld.acquire.gpu.u32 %0, [%1];" : "=r"(my) : "l"(gen));
            __threadfence();
            unsigned prev = atomicAdd(cnt, 1u);
            if (prev == NCTA_DIR - 1) {
                atomicExch(cnt, 0u);
                __threadfence();
                atomicAdd(gen, 1u);
            } else {
                unsigned cg;
                do {
                    __nanosleep(64);
                    asm volatile("ld.acquire.gpu.u32 %0, [%1];" : "=r"(cg) : "l"(gen));
                } while (cg == my);
            }
        }
        __syncthreads();
    }
}

// ---------------------------------------------------------------------------
// 6) Projection: state = tanh([hf|hb] @ Wp + bp)  (final h at parity 0)
// ---------------------------------------------------------------------------
__global__ void k_proj(const float* __restrict__ Wp, const float* __restrict__ bp,
                       float* __restrict__ out) {
    float* state = out + (size_t)Bd * Td * 2 * Ud;
    int b = blockIdx.x;

    __shared__ float cat[2 * Ud];
    for (int i = threadIdx.x; i < Ud; i += blockDim.x) {
        cat[i]      = g_h[0][0][b][i];
        cat[Ud + i] = g_h[1][0][b][i];
    }
    __syncthreads();

    for (int u = threadIdx.x; u < Ud; u += 256) {
        float acc = bp[u];
        for (int k = 0; k < 2 * Ud; k++)
            acc += cat[k] * Wp[(size_t)k * Ud + u];
        state[b * Ud + u] = tanhf(acc);
    }
}

// ---------------------------------------------------------------------------
extern "C" void kernel_launch(void* const* d_in, const int* in_sizes, int n_in,
                              void* d_out, int out_size) {
    const int*   x      = (const int*)d_in[0];
    const float* hidden = (const float*)d_in[1];
    const float* emb    = (const float*)d_in[2];
    const float* Wf     = (const float*)d_in[3];
    const float* Uf     = (const float*)d_in[4];
    const float* bf_in  = (const float*)d_in[5];
    const float* bf_rec = (const float*)d_in[6];
    const float* Wb     = (const float*)d_in[7];
    const float* Ub     = (const float*)d_in[8];
    const float* bb_in  = (const float*)d_in[9];
    const float* bb_rec = (const float*)d_in[10];
    const float* Wp     = (const float*)d_in[11];
    const float* bp     = (const float*)d_in[12];
    float* out = (float*)d_out;

    const int smem_bytes = 2 * 48 * USTRIDE * 2;   // 198144 (forces 1 CTA/SM)
    cudaFuncSetAttribute(k_recur, cudaFuncAttributeMaxDynamicSharedMemorySize,
                         smem_bytes);

    k_embed<<<Bd * Td, 256>>>(x, emb);
    k_init<<<(Bd * Ud) / 256, 256>>>(hidden);

    dim3 gu(Gd / 32, Ud / 32, 2);
    k_usplit<<<gu, dim3(32, 8)>>>(Uf, Ub);

    dim3 gi(Gd / 64, (Bd * Td) / 64, 2);
    k_ingemm<<<gi, 256>>>(Wf, Wb, bf_in, bb_in);

    k_recur<<<2 * NCTA_DIR, THREADS, smem_bytes>>>(x, bf_rec, bb_rec, out);

    k_proj<<<Bd, 256>>>(Wp, bp, out);
}

// round 10
// speedup vs baseline: 2.6475x; 1.1726x over previous
#include <cuda_runtime.h>
#include <cuda_bf16.h>
#include <math.h>

#define Bd 64
#define Td 256
#define Ed 256
#define Ud 1024
#define Gd 3072   // 3*Ud
#define NCTA_DIR 64
#define THREADS 256
#define NCHUNK 64          // 1024 / 16
#define USTRIDE 1032       // padded k-stride for U smem (conflict-free ldmatrix)

// ---------------- device scratch (allocation-free rule) ----------------
__device__ float g_gx[2][(size_t)Bd * Td * Gd];          // x@W + b_in
__device__ float g_h[2][2][Bd][Ud];                      // [dir][parity][b][u] fp32
// h in mma-A-fragment layout: [dir][parity][hi/lo][chunk][mtile][lane] -> 4 regs
__device__ uint4 g_hf[2][2][2][NCHUNK][4][32];
__device__ __nv_bfloat16 g_Ubf[2][2][Gd][Ud];            // [dir][hi/lo][n][k] (k-contig)
__device__ __nv_bfloat16 g_xebf[2][Bd * Td][Ed];         // [hi/lo][m][k]
__device__ __nv_bfloat16 g_Wbf[2][2][Gd][Ed];            // [dir][hi/lo][n][k]
__device__ unsigned g_cnt[2];

// ---------------- helpers ----------------
#define MMA_BF16(C, A0, A1, A2, A3, B0, B1)                                   \
    asm volatile(                                                             \
        "mma.sync.aligned.m16n8k16.row.col.f32.bf16.bf16.f32 "                \
        "{%0,%1,%2,%3}, {%4,%5,%6,%7}, {%8,%9}, {%0,%1,%2,%3};"               \
        : "+f"(C[0]), "+f"(C[1]), "+f"(C[2]), "+f"(C[3])                      \
        : "r"(A0), "r"(A1), "r"(A2), "r"(A3), "r"(B0), "r"(B1))

__device__ __forceinline__ void ldsm_x4(unsigned& r0, unsigned& r1,
                                        unsigned& r2, unsigned& r3,
                                        const void* p) {
    unsigned a = (unsigned)__cvta_generic_to_shared(p);
    asm volatile("ldmatrix.sync.aligned.m8n8.x4.shared.b16 {%0,%1,%2,%3}, [%4];"
                 : "=r"(r0), "=r"(r1), "=r"(r2), "=r"(r3) : "r"(a));
}
__device__ __forceinline__ void ldsm_x2(unsigned& r0, unsigned& r1, const void* p) {
    unsigned a = (unsigned)__cvta_generic_to_shared(p);
    asm volatile("ldmatrix.sync.aligned.m8n8.x2.shared.b16 {%0,%1}, [%2];"
                 : "=r"(r0), "=r"(r1) : "r"(a));
}

__device__ __forceinline__ float sigf(float a) {
    return 1.f / (1.f + __expf(-a));
}
__device__ __forceinline__ unsigned bf2u(float a, float b) {
    __nv_bfloat162 t;
    t.x = __float2bfloat16(a);
    t.y = __float2bfloat16(b);
    return *reinterpret_cast<unsigned*>(&t);
}

// ---------------------------------------------------------------------------
// 1) Embedding gather -> bf16 hi/lo split
// ---------------------------------------------------------------------------
__global__ void k_embed(const int* __restrict__ x, const float* __restrict__ emb) {
    int bt = blockIdx.x;
    int tok = x[bt];
    float v = emb[tok * Ed + threadIdx.x];
    __nv_bfloat16 hi = __float2bfloat16(v);
    __nv_bfloat16 lo = __float2bfloat16(v - __bfloat162float(hi));
    g_xebf[0][bt][threadIdx.x] = hi;
    g_xebf[1][bt][threadIdx.x] = lo;
}

// ---------------------------------------------------------------------------
// 2) Init hidden: fp32 buffers + fragment-layout hi/lo + barrier counters
// ---------------------------------------------------------------------------
__global__ void k_init(const float* __restrict__ hidden) {
    int i = blockIdx.x * blockDim.x + threadIdx.x;   // 65536
    if (i == 0) { g_cnt[0] = 0; g_cnt[1] = 0; }
    float v = hidden[i];
    int b = i >> 10, k = i & 1023;
    g_h[0][0][b][k] = v;
    g_h[1][0][b][k] = v;

    __nv_bfloat16 hi = __float2bfloat16(v);
    __nv_bfloat16 lo = __float2bfloat16(v - __bfloat162float(hi));

    int ch = k >> 4, cc = k & 15;
    int mtp = b >> 4, rt = b & 15;
    int gp = rt & 7, hir = rt >> 3;
    int tgp = (cc >> 1) & 3, chh = cc >> 3, pr = cc & 1;
    int lane = gp * 4 + tgp;
    int aidx = hir + 2 * chh;
    #pragma unroll
    for (int d = 0; d < 2; d++) {
        ((__nv_bfloat16*)&g_hf[d][0][0][ch][mtp][lane])[aidx * 2 + pr] = hi;
        ((__nv_bfloat16*)&g_hf[d][0][1][ch][mtp][lane])[aidx * 2 + pr] = lo;
    }
}

// ---------------------------------------------------------------------------
// 3a) U split+transpose: g_Ubf[dir][hi/lo][n][k] from U[k][n]
// ---------------------------------------------------------------------------
__global__ void k_usplit(const float* __restrict__ Uf, const float* __restrict__ Ub) {
    __shared__ float tile[32][33];
    int dir = blockIdx.z;
    const float* U = dir ? Ub : Uf;
    int n0 = blockIdx.x * 32, k0 = blockIdx.y * 32;

    for (int i = threadIdx.y; i < 32; i += 8)
        tile[i][threadIdx.x] = U[(size_t)(k0 + i) * Gd + n0 + threadIdx.x];
    __syncthreads();
    for (int i = threadIdx.y; i < 32; i += 8) {
        float u = tile[threadIdx.x][i];
        __nv_bfloat16 hi = __float2bfloat16(u);
        __nv_bfloat16 lo = __float2bfloat16(u - __bfloat162float(hi));
        g_Ubf[dir][0][n0 + i][k0 + threadIdx.x] = hi;
        g_Ubf[dir][1][n0 + i][k0 + threadIdx.x] = lo;
    }
}

// ---------------------------------------------------------------------------
// 3b) W split+transpose: g_Wbf[dir][hi/lo][n][k] from W[k][n]  (k in [0,256))
// ---------------------------------------------------------------------------
__global__ void k_wsplit(const float* __restrict__ Wf, const float* __restrict__ Wb) {
    __shared__ float tile[32][33];
    int dir = blockIdx.z;
    const float* W = dir ? Wb : Wf;
    int n0 = blockIdx.x * 32, k0 = blockIdx.y * 32;

    for (int i = threadIdx.y; i < 32; i += 8)
        tile[i][threadIdx.x] = W[(size_t)(k0 + i) * Gd + n0 + threadIdx.x];
    __syncthreads();
    for (int i = threadIdx.y; i < 32; i += 8) {
        float u = tile[threadIdx.x][i];
        __nv_bfloat16 hi = __float2bfloat16(u);
        __nv_bfloat16 lo = __float2bfloat16(u - __bfloat162float(hi));
        g_Wbf[dir][0][n0 + i][k0 + threadIdx.x] = hi;
        g_Wbf[dir][1][n0 + i][k0 + threadIdx.x] = lo;
    }
}

// ---------------------------------------------------------------------------
// 4) Input GEMM on tensor cores (bf16 3-split):
//    gx[dir] = xe (16384x256) @ W[dir] (256x3072) + b_in
//    CTA tile 128(m) x 64(n), K=256 in 16 k16 chunks. Warp: 32m x 32n.
// ---------------------------------------------------------------------------
__global__ void __launch_bounds__(256)
k_ingemm(const float* __restrict__ bf, const float* __restrict__ bb) {
    int dir = blockIdx.z;
    const float* bias = dir ? bb : bf;
    float* C = g_gx[dir];

    int n0 = blockIdx.x * 64;
    int m0 = blockIdx.y * 128;

    __shared__ __align__(16) __nv_bfloat16 As[2][128][24];   // [hi/lo][m][k16]
    __shared__ __align__(16) __nv_bfloat16 Bs[2][64][24];    // [hi/lo][n][k16]

    int tid = threadIdx.x;
    int wid = tid >> 5, lane = tid & 31;
    int mw = wid & 3, nw = wid >> 2;
    int g = lane >> 2, tg = lane & 3;

    // staging coords
    int a_row = tid >> 1, a_half = (tid & 1) * 8;          // 128 rows x 2 halves
    int b_n = tid & 63, b_half = ((tid >> 6) & 1) * 8, b_s = tid >> 7;

    float Cc[2][4][4];
    #pragma unroll
    for (int i = 0; i < 2; i++)
        #pragma unroll
        for (int j = 0; j < 4; j++)
            #pragma unroll
            for (int q = 0; q < 4; q++) Cc[i][j][q] = 0.f;

    for (int ch = 0; ch < 16; ch++) {
        int k0 = ch * 16;
        // stage A (both splits) and B
        #pragma unroll
        for (int s = 0; s < 2; s++)
            *(uint4*)&As[s][a_row][a_half] =
                *(const uint4*)&g_xebf[s][m0 + a_row][k0 + a_half];
        *(uint4*)&Bs[b_s][b_n][b_half] =
            *(const uint4*)&g_Wbf[dir][b_s][n0 + b_n][k0 + b_half];
        __syncthreads();

        #pragma unroll
        for (int mt2 = 0; mt2 < 2; mt2++) {
            unsigned ah0, ah1, ah2, ah3, al0, al1, al2, al3;
            int ar = mw * 32 + mt2 * 16 + (lane & 15);
            int ac = (lane >> 4) * 8;
            ldsm_x4(ah0, ah1, ah2, ah3, &As[0][ar][ac]);
            ldsm_x4(al0, al1, al2, al3, &As[1][ar][ac]);
            #pragma unroll
            for (int nt = 0; nt < 4; nt++) {
                unsigned bh0, bh1, bl0, bl1;
                int br = nw * 32 + nt * 8 + (lane & 7);
                int bc = ((lane >> 3) & 1) * 8;
                ldsm_x2(bh0, bh1, &Bs[0][br][bc]);
                ldsm_x2(bl0, bl1, &Bs[1][br][bc]);
                float* Cp = Cc[mt2][nt];
                MMA_BF16(Cp, ah0, ah1, ah2, ah3, bh0, bh1);
                MMA_BF16(Cp, ah0, ah1, ah2, ah3, bl0, bl1);
                MMA_BF16(Cp, al0, al1, al2, al3, bh0, bh1);
            }
        }
        __syncthreads();
    }

    #pragma unroll
    for (int mt2 = 0; mt2 < 2; mt2++) {
        #pragma unroll
        for (int nt = 0; nt < 4; nt++) {
            int n = n0 + nw * 32 + nt * 8 + 2 * tg;
            float b0 = bias[n], b1 = bias[n + 1];
            int mA = m0 + mw * 32 + mt2 * 16 + g;
            int mB = mA + 8;
            *(float2*)&C[(size_t)mA * Gd + n] =
                make_float2(Cc[mt2][nt][0] + b0, Cc[mt2][nt][1] + b1);
            *(float2*)&C[(size_t)mB * Gd + n] =
                make_float2(Cc[mt2][nt][2] + b0, Cc[mt2][nt][3] + b1);
        }
    }
}

// ---------------------------------------------------------------------------
// 5) Persistent recurrence: sync-free chunk loop, 8-deep A-frag prefetch,
//    monotonic grid barrier (counter zeroed by k_init each launch).
// ---------------------------------------------------------------------------
__global__ void __launch_bounds__(THREADS, 1)
k_recur(const int* __restrict__ x,
        const float* __restrict__ brf, const float* __restrict__ brb,
        float* __restrict__ out) {
    extern __shared__ unsigned char smraw[];
    __nv_bfloat16* Us = (__nv_bfloat16*)smraw;                 // [2][48][USTRIDE]

    int bx = blockIdx.x;
    int dir = bx >> 6;
    int c0 = (bx & 63) * 16;
    int ch_own = bx & 63;
    const float* brec = dir ? brb : brf;
    const float* gx = g_gx[dir];
    int tid = threadIdx.x;
    int wid = tid >> 5, lane = tid & 31;
    int mt = wid & 3, nh = wid >> 2;
    int g = lane >> 2, tg = lane & 3;

    // load U slice (bf16 hi/lo) once
    for (int idx = tid; idx < 2 * 48 * 1024; idx += THREADS) {
        int s = idx / 49152;
        int rem = idx - s * 49152;
        int j = rem >> 10;
        int k = rem & 1023;
        int gate = j >> 4, c = j & 15;
        Us[(s * 48 + j) * USTRIDE + k] = g_Ubf[dir][s][gate * 1024 + c0 + c][k];
    }

    int rl = mt * 16 + g, rh = rl + 8;           // batch rows
    int cb = c0 + nh * 8 + 2 * tg;               // h-col pair base (even)

    float2 Bz = *(const float2*)&brec[cb];
    float2 Br = *(const float2*)&brec[Ud + cb];
    float2 Bh = *(const float2*)&brec[2 * Ud + cb];

    int b_row_l = lane & 7;
    int b_col_l = ((lane >> 3) & 1) * 8;

    unsigned* cnt = &g_cnt[dir];

    __syncthreads();

    for (int s = 0; s < Td; s++) {
        int t = dir ? (Td - 1 - s) : s;
        int par = s & 1;

        // ---- prefetch epilogue operands ----
        size_t gl = (size_t)(rl * Td + t) * Gd + cb;
        size_t gh = (size_t)(rh * Td + t) * Gd + cb;
        float2 gz_l = __ldcg((const float2*)&gx[gl]);
        float2 gr_l = __ldcg((const float2*)&gx[gl + Ud]);
        float2 gh_l = __ldcg((const float2*)&gx[gl + 2 * Ud]);
        float2 gz_h = __ldcg((const float2*)&gx[gh]);
        float2 gr_h = __ldcg((const float2*)&gx[gh + Ud]);
        float2 gh_h = __ldcg((const float2*)&gx[gh + 2 * Ud]);
        float2 ho_l = __ldcg((const float2*)&g_h[dir][par][rl][cb]);
        float2 ho_h = __ldcg((const float2*)&g_h[dir][par][rh][cb]);
        int xl = __ldcg(&x[rl * Td + t]);
        int xh = __ldcg(&x[rh * Td + t]);

        float C0[4] = {0.f, 0.f, 0.f, 0.f};
        float C1[4] = {0.f, 0.f, 0.f, 0.f};
        float C2[4] = {0.f, 0.f, 0.f, 0.f};

        const uint4* hfA = &g_hf[dir][par][0][0][mt][lane];
        const uint4* hfL = &g_hf[dir][par][1][0][mt][lane];

        // 8-deep register prefetch of A fragments
        uint4 PA[8], PL[8];
        #pragma unroll
        for (int j = 0; j < 8; j++) {
            PA[j] = __ldcg(hfA + j * 128);
            PL[j] = __ldcg(hfL + j * 128);
        }

        #pragma unroll 8
        for (int ch = 0; ch < NCHUNK; ch++) {
            int sl = ch & 7;
            uint4 Ah = PA[sl];
            uint4 Al = PL[sl];
            if (ch + 8 < NCHUNK) {
                PA[sl] = __ldcg(hfA + (ch + 8) * 128);
                PL[sl] = __ldcg(hfL + (ch + 8) * 128);
            }

            int k0 = ch * 16;
            #pragma unroll
            for (int gt = 0; gt < 3; gt++) {
                int nt = gt * 2 + nh;
                unsigned bhi0, bhi1, blo0, blo1;
                ldsm_x2(bhi0, bhi1,
                        &Us[(0 * 48 + nt * 8 + b_row_l) * USTRIDE + k0 + b_col_l]);
                ldsm_x2(blo0, blo1,
                        &Us[(1 * 48 + nt * 8 + b_row_l) * USTRIDE + k0 + b_col_l]);
                float* Cp = (gt == 0) ? C0 : (gt == 1) ? C1 : C2;
                MMA_BF16(Cp, Ah.x, Ah.y, Ah.z, Ah.w, bhi0, bhi1);
                MMA_BF16(Cp, Ah.x, Ah.y, Ah.z, Ah.w, blo0, blo1);
                MMA_BF16(Cp, Al.x, Al.y, Al.z, Al.w, bhi0, bhi1);
            }
        }

        // ---- epilogue ----
        float hn[4];
        {
            float z0 = sigf(gz_l.x + C0[0] + Bz.x);
            float z1 = sigf(gz_l.y + C0[1] + Bz.y);
            float r0 = sigf(gr_l.x + C1[0] + Br.x);
            float r1 = sigf(gr_l.y + C1[1] + Br.y);
            float t0 = tanhf(gh_l.x + r0 * (C2[0] + Bh.x));
            float t1 = tanhf(gh_l.y + r1 * (C2[1] + Bh.y));
            hn[0] = z0 * ho_l.x + (1.f - z0) * t0;
            hn[1] = z1 * ho_l.y + (1.f - z1) * t1;
            if (xl == 0) { hn[0] = ho_l.x; hn[1] = ho_l.y; }

            float z2 = sigf(gz_h.x + C0[2] + Bz.x);
            float z3 = sigf(gz_h.y + C0[3] + Bz.y);
            float r2 = sigf(gr_h.x + C1[2] + Br.x);
            float r3 = sigf(gr_h.y + C1[3] + Br.y);
            float t2 = tanhf(gh_h.x + r2 * (C2[2] + Bh.x));
            float t3 = tanhf(gh_h.y + r3 * (C2[3] + Bh.y));
            hn[2] = z2 * ho_h.x + (1.f - z2) * t2;
            hn[3] = z3 * ho_h.y + (1.f - z3) * t3;
            if (xh == 0) { hn[2] = ho_h.x; hn[3] = ho_h.y; }
        }

        int pn = par ^ 1;
        *(float2*)&g_h[dir][pn][rl][cb] = make_float2(hn[0], hn[1]);
        *(float2*)&g_h[dir][pn][rh][cb] = make_float2(hn[2], hn[3]);

        // write next-step A fragments (hi/lo) for this CTA's chunk
        {
            float f0 = hn[0], f1 = hn[1], f2 = hn[2], f3 = hn[3];
            __nv_bfloat16 h0 = __float2bfloat16(f0);
            __nv_bfloat16 h1 = __float2bfloat16(f1);
            __nv_bfloat16 h2 = __float2bfloat16(f2);
            __nv_bfloat16 h3 = __float2bfloat16(f3);
            uint2 vhi, vlo;
            {
                __nv_bfloat162 p0; p0.x = h0; p0.y = h1;
                __nv_bfloat162 p1; p1.x = h2; p1.y = h3;
                vhi.x = *reinterpret_cast<unsigned*>(&p0);
                vhi.y = *reinterpret_cast<unsigned*>(&p1);
            }
            vlo.x = bf2u(f0 - __bfloat162float(h0), f1 - __bfloat162float(h1));
            vlo.y = bf2u(f2 - __bfloat162float(h2), f3 - __bfloat162float(h3));

            unsigned* fp_hi = (unsigned*)&g_hf[dir][pn][0][ch_own][mt][lane];
            unsigned* fp_lo = (unsigned*)&g_hf[dir][pn][1][ch_own][mt][lane];
            *(uint2*)(fp_hi + 2 * nh) = vhi;
            *(uint2*)(fp_lo + 2 * nh) = vlo;
        }

        #pragma unroll
        for (int rr = 0; rr < 2; rr++) {
            int b = rr ? rh : rl;
            *(float2*)&out[(size_t)(b * Td + t) * (2 * Ud) + dir * Ud + cb] =
                make_float2(hn[rr * 2], hn[rr * 2 + 1]);
        }

        // ---- per-direction monotonic grid barrier ----
        __syncthreads();
        if (tid == 0) {
            __threadfence();
            atomicAdd(cnt, 1u);
            unsigned target = (unsigned)(s + 1) * NCTA_DIR;
            unsigned c;
            asm volatile("ld.acquire.gpu.u32 %0, [%1];" : "=r"(c) : "l"(cnt));
            while (c < target) {
                __nanosleep(32);
                asm volatile("ld.acquire.gpu.u32 %0, [%1];" : "=r"(c) : "l"(cnt));
            }
        }
        __syncthreads();
    }
}

// ---------------------------------------------------------------------------
// 6) Projection: state = tanh([hf|hb] @ Wp + bp)  (final h at parity 0)
// ---------------------------------------------------------------------------
__global__ void k_proj(const float* __restrict__ Wp, const float* __restrict__ bp,
                       float* __restrict__ out) {
    float* state = out + (size_t)Bd * Td * 2 * Ud;
    int b = blockIdx.x;

    __shared__ float cat[2 * Ud];
    for (int i = threadIdx.x; i < Ud; i += blockDim.x) {
        cat[i]      = g_h[0][0][b][i];
        cat[Ud + i] = g_h[1][0][b][i];
    }
    __syncthreads();

    for (int u = threadIdx.x; u < Ud; u += 256) {
        float acc = bp[u];
        for (int k = 0; k < 2 * Ud; k++)
            acc += cat[k] * Wp[(size_t)k * Ud + u];
        state[b * Ud + u] = tanhf(acc);
    }
}

// ---------------------------------------------------------------------------
extern "C" void kernel_launch(void* const* d_in, const int* in_sizes, int n_in,
                              void* d_out, int out_size) {
    const int*   x      = (const int*)d_in[0];
    const float* hidden = (const float*)d_in[1];
    const float* emb    = (const float*)d_in[2];
    const float* Wf     = (const float*)d_in[3];
    const float* Uf     = (const float*)d_in[4];
    const float* bf_in  = (const float*)d_in[5];
    const float* bf_rec = (const float*)d_in[6];
    const float* Wb     = (const float*)d_in[7];
    const float* Ub     = (const float*)d_in[8];
    const float* bb_in  = (const float*)d_in[9];
    const float* bb_rec = (const float*)d_in[10];
    const float* Wp     = (const float*)d_in[11];
    const float* bp     = (const float*)d_in[12];
    float* out = (float*)d_out;

    const int smem_bytes = 2 * 48 * USTRIDE * 2;   // 198144 (forces 1 CTA/SM)
    cudaFuncSetAttribute(k_recur, cudaFuncAttributeMaxDynamicSharedMemorySize,
                         smem_bytes);

    k_embed<<<Bd * Td, 256>>>(x, emb);
    k_init<<<(Bd * Ud) / 256, 256>>>(hidden);

    dim3 gu(Gd / 32, Ud / 32, 2);
    k_usplit<<<gu, dim3(32, 8)>>>(Uf, Ub);

    dim3 gw(Gd / 32, Ed / 32, 2);
    k_wsplit<<<gw, dim3(32, 8)>>>(Wf, Wb);

    dim3 gi(Gd / 64, (Bd * Td) / 128, 2);
    k_ingemm<<<gi, 256>>>(bf_in, bb_in);

    k_recur<<<2 * NCTA_DIR, THREADS, smem_bytes>>>(x, bf_rec, bb_rec, out);

    k_proj<<<Bd, 256>>>(Wp, bp, out);
}

// round 11
// speedup vs baseline: 2.7797x; 1.0499x over previous
#include <cuda_runtime.h>
#include <cuda_bf16.h>
#include <math.h>

#define Bd 64
#define Td 256
#define Ed 256
#define Ud 1024
#define Gd 3072   // 3*Ud
#define NCTA_DIR 64
#define THREADS 256
#define NCHUNK 64          // 1024 / 16
#define USTRIDE 1032       // padded k-stride for U smem (conflict-free ldmatrix)
#define USIZE (2 * 48 * USTRIDE * 2)          // 198144 bytes
#define REDSIZE (2 * 2 * 2 * 6 * 32 * 16)     // 24576 bytes

// ---------------- device scratch (allocation-free rule) ----------------
__device__ float g_gx[2][(size_t)Bd * Td * Gd];          // x@W + b_in
__device__ float g_h[2][2][Bd][Ud];                      // [dir][parity][b][u] fp32
// h in mma-A-fragment layout: [dir][parity][hi/lo][chunk][mtile][lane] -> 4 regs
__device__ uint4 g_hf[2][2][2][NCHUNK][4][32];
__device__ __nv_bfloat16 g_Ubf[2][2][Gd][Ud];            // [dir][hi/lo][n][k] (k-contig)
__device__ __nv_bfloat16 g_xebf[2][Bd * Td][Ed];         // [hi/lo][m][k]
__device__ __nv_bfloat16 g_Wbf[2][2][Gd][Ed];            // [dir][hi/lo][n][k]
__device__ unsigned g_cnt[2];

// ---------------- helpers ----------------
#define MMA_BF16(C, A0, A1, A2, A3, B0, B1)                                   \
    asm volatile(                                                             \
        "mma.sync.aligned.m16n8k16.row.col.f32.bf16.bf16.f32 "                \
        "{%0,%1,%2,%3}, {%4,%5,%6,%7}, {%8,%9}, {%0,%1,%2,%3};"               \
        : "+f"(C[0]), "+f"(C[1]), "+f"(C[2]), "+f"(C[3])                      \
        : "r"(A0), "r"(A1), "r"(A2), "r"(A3), "r"(B0), "r"(B1))

__device__ __forceinline__ void ldsm_x4(unsigned& r0, unsigned& r1,
                                        unsigned& r2, unsigned& r3,
                                        const void* p) {
    unsigned a = (unsigned)__cvta_generic_to_shared(p);
    asm volatile("ldmatrix.sync.aligned.m8n8.x4.shared.b16 {%0,%1,%2,%3}, [%4];"
                 : "=r"(r0), "=r"(r1), "=r"(r2), "=r"(r3) : "r"(a));
}
__device__ __forceinline__ void ldsm_x2(unsigned& r0, unsigned& r1, const void* p) {
    unsigned a = (unsigned)__cvta_generic_to_shared(p);
    asm volatile("ldmatrix.sync.aligned.m8n8.x2.shared.b16 {%0,%1}, [%2];"
                 : "=r"(r0), "=r"(r1) : "r"(a));
}

__device__ __forceinline__ float sigf(float a) {
    return 1.f / (1.f + __expf(-a));
}
__device__ __forceinline__ unsigned bf2u(float a, float b) {
    __nv_bfloat162 t;
    t.x = __float2bfloat16(a);
    t.y = __float2bfloat16(b);
    return *reinterpret_cast<unsigned*>(&t);
}

// ---------------------------------------------------------------------------
// 1) Embedding gather -> bf16 hi/lo split
// ---------------------------------------------------------------------------
__global__ void k_embed(const int* __restrict__ x, const float* __restrict__ emb) {
    int bt = blockIdx.x;
    int tok = x[bt];
    float v = emb[tok * Ed + threadIdx.x];
    __nv_bfloat16 hi = __float2bfloat16(v);
    __nv_bfloat16 lo = __float2bfloat16(v - __bfloat162float(hi));
    g_xebf[0][bt][threadIdx.x] = hi;
    g_xebf[1][bt][threadIdx.x] = lo;
}

// ---------------------------------------------------------------------------
// 2) Init hidden: fp32 buffers + fragment-layout hi/lo + barrier counters
// ---------------------------------------------------------------------------
__global__ void k_init(const float* __restrict__ hidden) {
    int i = blockIdx.x * blockDim.x + threadIdx.x;   // 65536
    if (i == 0) { g_cnt[0] = 0; g_cnt[1] = 0; }
    float v = hidden[i];
    int b = i >> 10, k = i & 1023;
    g_h[0][0][b][k] = v;
    g_h[1][0][b][k] = v;

    __nv_bfloat16 hi = __float2bfloat16(v);
    __nv_bfloat16 lo = __float2bfloat16(v - __bfloat162float(hi));

    int ch = k >> 4, cc = k & 15;
    int mtp = b >> 4, rt = b & 15;
    int gp = rt & 7, hir = rt >> 3;
    int tgp = (cc >> 1) & 3, chh = cc >> 3, pr = cc & 1;
    int lane = gp * 4 + tgp;
    int aidx = hir + 2 * chh;
    #pragma unroll
    for (int d = 0; d < 2; d++) {
        ((__nv_bfloat16*)&g_hf[d][0][0][ch][mtp][lane])[aidx * 2 + pr] = hi;
        ((__nv_bfloat16*)&g_hf[d][0][1][ch][mtp][lane])[aidx * 2 + pr] = lo;
    }
}

// ---------------------------------------------------------------------------
// 3a) U split+transpose: g_Ubf[dir][hi/lo][n][k] from U[k][n]
// ---------------------------------------------------------------------------
__global__ void k_usplit(const float* __restrict__ Uf, const float* __restrict__ Ub) {
    __shared__ float tile[32][33];
    int dir = blockIdx.z;
    const float* U = dir ? Ub : Uf;
    int n0 = blockIdx.x * 32, k0 = blockIdx.y * 32;

    for (int i = threadIdx.y; i < 32; i += 8)
        tile[i][threadIdx.x] = U[(size_t)(k0 + i) * Gd + n0 + threadIdx.x];
    __syncthreads();
    for (int i = threadIdx.y; i < 32; i += 8) {
        float u = tile[threadIdx.x][i];
        __nv_bfloat16 hi = __float2bfloat16(u);
        __nv_bfloat16 lo = __float2bfloat16(u - __bfloat162float(hi));
        g_Ubf[dir][0][n0 + i][k0 + threadIdx.x] = hi;
        g_Ubf[dir][1][n0 + i][k0 + threadIdx.x] = lo;
    }
}

// ---------------------------------------------------------------------------
// 3b) W split+transpose: g_Wbf[dir][hi/lo][n][k] from W[k][n]  (k in [0,256))
// ---------------------------------------------------------------------------
__global__ void k_wsplit(const float* __restrict__ Wf, const float* __restrict__ Wb) {
    __shared__ float tile[32][33];
    int dir = blockIdx.z;
    const float* W = dir ? Wb : Wf;
    int n0 = blockIdx.x * 32, k0 = blockIdx.y * 32;

    for (int i = threadIdx.y; i < 32; i += 8)
        tile[i][threadIdx.x] = W[(size_t)(k0 + i) * Gd + n0 + threadIdx.x];
    __syncthreads();
    for (int i = threadIdx.y; i < 32; i += 8) {
        float u = tile[threadIdx.x][i];
        __nv_bfloat16 hi = __float2bfloat16(u);
        __nv_bfloat16 lo = __float2bfloat16(u - __bfloat162float(hi));
        g_Wbf[dir][0][n0 + i][k0 + threadIdx.x] = hi;
        g_Wbf[dir][1][n0 + i][k0 + threadIdx.x] = lo;
    }
}

// ---------------------------------------------------------------------------
// 4) Input GEMM on tensor cores (bf16 3-split):
//    gx[dir] = xe (16384x256) @ W[dir] (256x3072) + b_in
// ---------------------------------------------------------------------------
__global__ void __launch_bounds__(256)
k_ingemm(const float* __restrict__ bf, const float* __restrict__ bb) {
    int dir = blockIdx.z;
    const float* bias = dir ? bb : bf;
    float* C = g_gx[dir];

    int n0 = blockIdx.x * 64;
    int m0 = blockIdx.y * 128;

    __shared__ __align__(16) __nv_bfloat16 As[2][128][24];   // [hi/lo][m][k16]
    __shared__ __align__(16) __nv_bfloat16 Bs[2][64][24];    // [hi/lo][n][k16]

    int tid = threadIdx.x;
    int wid = tid >> 5, lane = tid & 31;
    int mw = wid & 3, nw = wid >> 2;
    int g = lane >> 2, tg = lane & 3;

    int a_row = tid >> 1, a_half = (tid & 1) * 8;
    int b_n = tid & 63, b_half = ((tid >> 6) & 1) * 8, b_s = tid >> 7;

    float Cc[2][4][4];
    #pragma unroll
    for (int i = 0; i < 2; i++)
        #pragma unroll
        for (int j = 0; j < 4; j++)
            #pragma unroll
            for (int q = 0; q < 4; q++) Cc[i][j][q] = 0.f;

    for (int ch = 0; ch < 16; ch++) {
        int k0 = ch * 16;
        #pragma unroll
        for (int s = 0; s < 2; s++)
            *(uint4*)&As[s][a_row][a_half] =
                *(const uint4*)&g_xebf[s][m0 + a_row][k0 + a_half];
        *(uint4*)&Bs[b_s][b_n][b_half] =
            *(const uint4*)&g_Wbf[dir][b_s][n0 + b_n][k0 + b_half];
        __syncthreads();

        #pragma unroll
        for (int mt2 = 0; mt2 < 2; mt2++) {
            unsigned ah0, ah1, ah2, ah3, al0, al1, al2, al3;
            int ar = mw * 32 + mt2 * 16 + (lane & 15);
            int ac = (lane >> 4) * 8;
            ldsm_x4(ah0, ah1, ah2, ah3, &As[0][ar][ac]);
            ldsm_x4(al0, al1, al2, al3, &As[1][ar][ac]);
            #pragma unroll
            for (int nt = 0; nt < 4; nt++) {
                unsigned bh0, bh1, bl0, bl1;
                int br = nw * 32 + nt * 8 + (lane & 7);
                int bc = ((lane >> 3) & 1) * 8;
                ldsm_x2(bh0, bh1, &Bs[0][br][bc]);
                ldsm_x2(bl0, bl1, &Bs[1][br][bc]);
                float* Cp = Cc[mt2][nt];
                MMA_BF16(Cp, ah0, ah1, ah2, ah3, bh0, bh1);
                MMA_BF16(Cp, ah0, ah1, ah2, ah3, bl0, bl1);
                MMA_BF16(Cp, al0, al1, al2, al3, bh0, bh1);
            }
        }
        __syncthreads();
    }

    #pragma unroll
    for (int mt2 = 0; mt2 < 2; mt2++) {
        #pragma unroll
        for (int nt = 0; nt < 4; nt++) {
            int n = n0 + nw * 32 + nt * 8 + 2 * tg;
            float b0 = bias[n], b1 = bias[n + 1];
            int mA = m0 + mw * 32 + mt2 * 16 + g;
            int mB = mA + 8;
            *(float2*)&C[(size_t)mA * Gd + n] =
                make_float2(Cc[mt2][nt][0] + b0, Cc[mt2][nt][1] + b1);
            *(float2*)&C[(size_t)mB * Gd + n] =
                make_float2(Cc[mt2][nt][2] + b0, Cc[mt2][nt][3] + b1);
        }
    }
}

// ---------------------------------------------------------------------------
// 5) Persistent recurrence. GEMM warp layout (mg,kq): warp owns m-rows
//    [mg*32, mg*32+32) x k-chunks [kq*16, kq*16+16), ALL 6 n-tiles.
//    -> each A fragment loaded once per CTA (L2 traffic halved),
//    -> B hi+lo fused in one ldmatrix.x4, smem redundancy halved.
//    Partial C's reduced across kq warps via smem tree, final C broadcast
//    through smem; epilogue runs in the proven (mt,nh) roles unchanged.
// ---------------------------------------------------------------------------
__global__ void __launch_bounds__(THREADS, 1)
k_recur(const int* __restrict__ x,
        const float* __restrict__ brf, const float* __restrict__ brb,
        float* __restrict__ out) {
    extern __shared__ unsigned char smraw[];
    __nv_bfloat16* Us = (__nv_bfloat16*)smraw;               // [2][48][USTRIDE]
    float4* red = (float4*)(smraw + USIZE);                  // [mg][slot][mt2][nt][lane]

    int bx = blockIdx.x;
    int dir = bx >> 6;
    int c0 = (bx & 63) * 16;
    int ch_own = bx & 63;
    const float* brec = dir ? brb : brf;
    const float* gx = g_gx[dir];
    int tid = threadIdx.x;
    int wid = tid >> 5, lane = tid & 31;
    // epilogue roles (same as R10)
    int mt = wid & 3, nh = wid >> 2;
    int g = lane >> 2, tg = lane & 3;
    // GEMM roles
    int mg = wid >> 2, kq = wid & 3;

    // load U slice (bf16 hi/lo) once
    for (int idx = tid; idx < 2 * 48 * 1024; idx += THREADS) {
        int s = idx / 49152;
        int rem = idx - s * 49152;
        int j = rem >> 10;
        int k = rem & 1023;
        int gate = j >> 4, c = j & 15;
        Us[(s * 48 + j) * USTRIDE + k] = g_Ubf[dir][s][gate * 1024 + c0 + c][k];
    }

    int rl = mt * 16 + g, rh = rl + 8;           // epilogue batch rows
    int cb = c0 + nh * 8 + 2 * tg;               // h-col pair base (even)

    float2 Bz = *(const float2*)&brec[cb];
    float2 Br = *(const float2*)&brec[Ud + cb];
    float2 Bh = *(const float2*)&brec[2 * Ud + cb];

    // B ldmatrix.x4 per-lane source: groups of 8 lanes ->
    //   q=0: hi k-low, q=1: hi k-high, q=2: lo k-low, q=3: lo k-high
    int bq = lane >> 3, brr = lane & 7;
    int bsplit = bq >> 1;
    int bkhalf = (bq & 1) * 8;

    unsigned* cnt = &g_cnt[dir];

    // reduction buffer index helper strides (in float4 units)
    // idx = (((mg*2 + slot)*2 + mt2)*6 + nt)*32 + lane
    __syncthreads();

    for (int s = 0; s < Td; s++) {
        int t = dir ? (Td - 1 - s) : s;
        int par = s & 1;

        // ---- prefetch epilogue operands (old roles) ----
        size_t gl = (size_t)(rl * Td + t) * Gd + cb;
        size_t gh = (size_t)(rh * Td + t) * Gd + cb;
        float2 gz_l = __ldcg((const float2*)&gx[gl]);
        float2 gr_l = __ldcg((const float2*)&gx[gl + Ud]);
        float2 gh_l = __ldcg((const float2*)&gx[gl + 2 * Ud]);
        float2 gz_h = __ldcg((const float2*)&gx[gh]);
        float2 gr_h = __ldcg((const float2*)&gx[gh + Ud]);
        float2 gh_h = __ldcg((const float2*)&gx[gh + 2 * Ud]);
        float2 ho_l = __ldcg((const float2*)&g_h[dir][par][rl][cb]);
        float2 ho_h = __ldcg((const float2*)&g_h[dir][par][rh][cb]);
        int xl = __ldcg(&x[rl * Td + t]);
        int xh = __ldcg(&x[rh * Td + t]);

        // ---- GEMM: partial gr over chunks [kq*16, kq*16+16) ----
        float Cc[2][6][4];
        #pragma unroll
        for (int i = 0; i < 2; i++)
            #pragma unroll
            for (int j = 0; j < 6; j++)
                #pragma unroll
                for (int q = 0; q < 4; q++) Cc[i][j][q] = 0.f;

        const uint4* hf0 = &g_hf[dir][par][0][0][mg * 2][lane];  // hi, mt2=0
        const uint4* hf1 = &g_hf[dir][par][1][0][mg * 2][lane];  // lo, mt2=0
        int chBase = kq * 16;

        uint4 P[4][4];   // [depth][mt2*2 + split]
        #pragma unroll
        for (int j = 0; j < 4; j++) {
            const uint4* ph = hf0 + (size_t)(chBase + j) * 128;
            const uint4* pl = hf1 + (size_t)(chBase + j) * 128;
            P[j][0] = __ldcg(ph);      P[j][1] = __ldcg(pl);
            P[j][2] = __ldcg(ph + 32); P[j][3] = __ldcg(pl + 32);
        }

        #pragma unroll 4
        for (int ci = 0; ci < 16; ci++) {
            int sl = ci & 3;
            uint4 A0h = P[sl][0], A0l = P[sl][1];
            uint4 A1h = P[sl][2], A1l = P[sl][3];
            if (ci + 4 < 16) {
                const uint4* ph = hf0 + (size_t)(chBase + ci + 4) * 128;
                const uint4* pl = hf1 + (size_t)(chBase + ci + 4) * 128;
                P[sl][0] = __ldcg(ph);      P[sl][1] = __ldcg(pl);
                P[sl][2] = __ldcg(ph + 32); P[sl][3] = __ldcg(pl + 32);
            }

            int k0 = (chBase + ci) * 16;
            #pragma unroll
            for (int nt = 0; nt < 6; nt++) {
                unsigned bh0, bh1, bl0, bl1;
                ldsm_x4(bh0, bh1, bl0, bl1,
                        &Us[(bsplit * 48 + nt * 8 + brr) * USTRIDE + k0 + bkhalf]);
                float* Cp0 = Cc[0][nt];
                float* Cp1 = Cc[1][nt];
                MMA_BF16(Cp0, A0h.x, A0h.y, A0h.z, A0h.w, bh0, bh1);
                MMA_BF16(Cp0, A0h.x, A0h.y, A0h.z, A0h.w, bl0, bl1);
                MMA_BF16(Cp0, A0l.x, A0l.y, A0l.z, A0l.w, bh0, bh1);
                MMA_BF16(Cp1, A1h.x, A1h.y, A1h.z, A1h.w, bh0, bh1);
                MMA_BF16(Cp1, A1h.x, A1h.y, A1h.z, A1h.w, bl0, bl1);
                MMA_BF16(Cp1, A1l.x, A1l.y, A1l.z, A1l.w, bh0, bh1);
            }
        }

        // ---- reduce partials across kq warps (3-round smem tree) ----
        #define RIDX(MG, SLOT, MT2, NT) \
            (((((MG) * 2 + (SLOT)) * 2 + (MT2)) * 6 + (NT)) * 32 + lane)

        if (kq & 1) {
            int slot = kq >> 1;
            #pragma unroll
            for (int mt2 = 0; mt2 < 2; mt2++)
                #pragma unroll
                for (int nt = 0; nt < 6; nt++)
                    red[RIDX(mg, slot, mt2, nt)] =
                        make_float4(Cc[mt2][nt][0], Cc[mt2][nt][1],
                                    Cc[mt2][nt][2], Cc[mt2][nt][3]);
        }
        __syncthreads();
        if (!(kq & 1)) {
            int slot = kq >> 1;
            #pragma unroll
            for (int mt2 = 0; mt2 < 2; mt2++)
                #pragma unroll
                for (int nt = 0; nt < 6; nt++) {
                    float4 v = red[RIDX(mg, slot, mt2, nt)];
                    Cc[mt2][nt][0] += v.x; Cc[mt2][nt][1] += v.y;
                    Cc[mt2][nt][2] += v.z; Cc[mt2][nt][3] += v.w;
                }
        }
        __syncthreads();
        if (kq == 2) {
            #pragma unroll
            for (int mt2 = 0; mt2 < 2; mt2++)
                #pragma unroll
                for (int nt = 0; nt < 6; nt++)
                    red[RIDX(mg, 0, mt2, nt)] =
                        make_float4(Cc[mt2][nt][0], Cc[mt2][nt][1],
                                    Cc[mt2][nt][2], Cc[mt2][nt][3]);
        }
        __syncthreads();
        if (kq == 0) {
            #pragma unroll
            for (int mt2 = 0; mt2 < 2; mt2++)
                #pragma unroll
                for (int nt = 0; nt < 6; nt++) {
                    float4 v = red[RIDX(mg, 0, mt2, nt)];
                    red[RIDX(mg, 1, mt2, nt)] =
                        make_float4(Cc[mt2][nt][0] + v.x, Cc[mt2][nt][1] + v.y,
                                    Cc[mt2][nt][2] + v.z, Cc[mt2][nt][3] + v.w);
                }
        }
        __syncthreads();

        // ---- read final C in epilogue roles (mt, nh) ----
        float C0[4], C1[4], C2[4];
        {
            float4 v0 = red[RIDX(mt >> 1, 1, mt & 1, 0 * 2 + nh)];
            float4 v1 = red[RIDX(mt >> 1, 1, mt & 1, 1 * 2 + nh)];
            float4 v2 = red[RIDX(mt >> 1, 1, mt & 1, 2 * 2 + nh)];
            C0[0] = v0.x; C0[1] = v0.y; C0[2] = v0.z; C0[3] = v0.w;
            C1[0] = v1.x; C1[1] = v1.y; C1[2] = v1.z; C1[3] = v1.w;
            C2[0] = v2.x; C2[1] = v2.y; C2[2] = v2.z; C2[3] = v2.w;
        }
        #undef RIDX

        // ---- epilogue (identical to R10) ----
        float hn[4];
        {
            float z0 = sigf(gz_l.x + C0[0] + Bz.x);
            float z1 = sigf(gz_l.y + C0[1] + Bz.y);
            float r0 = sigf(gr_l.x + C1[0] + Br.x);
            float r1 = sigf(gr_l.y + C1[1] + Br.y);
            float t0 = tanhf(gh_l.x + r0 * (C2[0] + Bh.x));
            float t1 = tanhf(gh_l.y + r1 * (C2[1] + Bh.y));
            hn[0] = z0 * ho_l.x + (1.f - z0) * t0;
            hn[1] = z1 * ho_l.y + (1.f - z1) * t1;
            if (xl == 0) { hn[0] = ho_l.x; hn[1] = ho_l.y; }

            float z2 = sigf(gz_h.x + C0[2] + Bz.x);
            float z3 = sigf(gz_h.y + C0[3] + Bz.y);
            float r2 = sigf(gr_h.x + C1[2] + Br.x);
            float r3 = sigf(gr_h.y + C1[3] + Br.y);
            float t2 = tanhf(gh_h.x + r2 * (C2[2] + Bh.x));
            float t3 = tanhf(gh_h.y + r3 * (C2[3] + Bh.y));
            hn[2] = z2 * ho_h.x + (1.f - z2) * t2;
            hn[3] = z3 * ho_h.y + (1.f - z3) * t3;
            if (xh == 0) { hn[2] = ho_h.x; hn[3] = ho_h.y; }
        }

        int pn = par ^ 1;
        *(float2*)&g_h[dir][pn][rl][cb] = make_float2(hn[0], hn[1]);
        *(float2*)&g_h[dir][pn][rh][cb] = make_float2(hn[2], hn[3]);

        {
            float f0 = hn[0], f1 = hn[1], f2 = hn[2], f3 = hn[3];
            __nv_bfloat16 h0 = __float2bfloat16(f0);
            __nv_bfloat16 h1 = __float2bfloat16(f1);
            __nv_bfloat16 h2 = __float2bfloat16(f2);
            __nv_bfloat16 h3 = __float2bfloat16(f3);
            uint2 vhi, vlo;
            {
                __nv_bfloat162 p0; p0.x = h0; p0.y = h1;
                __nv_bfloat162 p1; p1.x = h2; p1.y = h3;
                vhi.x = *reinterpret_cast<unsigned*>(&p0);
                vhi.y = *reinterpret_cast<unsigned*>(&p1);
            }
            vlo.x = bf2u(f0 - __bfloat162float(h0), f1 - __bfloat162float(h1));
            vlo.y = bf2u(f2 - __bfloat162float(h2), f3 - __bfloat162float(h3));

            unsigned* fp_hi = (unsigned*)&g_hf[dir][pn][0][ch_own][mt][lane];
            unsigned* fp_lo = (unsigned*)&g_hf[dir][pn][1][ch_own][mt][lane];
            *(uint2*)(fp_hi + 2 * nh) = vhi;
            *(uint2*)(fp_lo + 2 * nh) = vlo;
        }

        #pragma unroll
        for (int rr = 0; rr < 2; rr++) {
            int b = rr ? rh : rl;
            *(float2*)&out[(size_t)(b * Td + t) * (2 * Ud) + dir * Ud + cb] =
                make_float2(hn[rr * 2], hn[rr * 2 + 1]);
        }

        // ---- per-direction monotonic grid barrier ----
        __syncthreads();
        if (tid == 0) {
            __threadfence();
            atomicAdd(cnt, 1u);
            unsigned target = (unsigned)(s + 1) * NCTA_DIR;
            unsigned c;
            asm volatile("ld.acquire.gpu.u32 %0, [%1];" : "=r"(c) : "l"(cnt));
            while (c < target) {
                __nanosleep(32);
                asm volatile("ld.acquire.gpu.u32 %0, [%1];" : "=r"(c) : "l"(cnt));
            }
        }
        __syncthreads();
    }
}

// ---------------------------------------------------------------------------
// 6) Projection: state = tanh([hf|hb] @ Wp + bp)  (final h at parity 0)
// ---------------------------------------------------------------------------
__global__ void k_proj(const float* __restrict__ Wp, const float* __restrict__ bp,
                       float* __restrict__ out) {
    float* state = out + (size_t)Bd * Td * 2 * Ud;
    int b = blockIdx.x;

    __shared__ float cat[2 * Ud];
    for (int i = threadIdx.x; i < Ud; i += blockDim.x) {
        cat[i]      = g_h[0][0][b][i];
        cat[Ud + i] = g_h[1][0][b][i];
    }
    __syncthreads();

    for (int u = threadIdx.x; u < Ud; u += 256) {
        float acc = bp[u];
        for (int k = 0; k < 2 * Ud; k++)
            acc += cat[k] * Wp[(size_t)k * Ud + u];
        state[b * Ud + u] = tanhf(acc);
    }
}

// ---------------------------------------------------------------------------
extern "C" void kernel_launch(void* const* d_in, const int* in_sizes, int n_in,
                              void* d_out, int out_size) {
    const int*   x      = (const int*)d_in[0];
    const float* hidden = (const float*)d_in[1];
    const float* emb    = (const float*)d_in[2];
    const float* Wf     = (const float*)d_in[3];
    const float* Uf     = (const float*)d_in[4];
    const float* bf_in  = (const float*)d_in[5];
    const float* bf_rec = (const float*)d_in[6];
    const float* Wb     = (const float*)d_in[7];
    const float* Ub     = (const float*)d_in[8];
    const float* bb_in  = (const float*)d_in[9];
    const float* bb_rec = (const float*)d_in[10];
    const float* Wp     = (const float*)d_in[11];
    const float* bp     = (const float*)d_in[12];
    float* out = (float*)d_out;

    const int smem_bytes = USIZE + REDSIZE;   // 222720
    cudaFuncSetAttribute(k_recur, cudaFuncAttributeMaxDynamicSharedMemorySize,
                         smem_bytes);

    k_embed<<<Bd * Td, 256>>>(x, emb);
    k_init<<<(Bd * Ud) / 256, 256>>>(hidden);

    dim3 gu(Gd / 32, Ud / 32, 2);
    k_usplit<<<gu, dim3(32, 8)>>>(Uf, Ub);

    dim3 gw(Gd / 32, Ed / 32, 2);
    k_wsplit<<<gw, dim3(32, 8)>>>(Wf, Wb);

    dim3 gi(Gd / 64, (Bd * Td) / 128, 2);
    k_ingemm<<<gi, 256>>>(bf_in, bb_in);

    k_recur<<<2 * NCTA_DIR, THREADS, smem_bytes>>>(x, bf_rec, bb_rec, out);

    k_proj<<<Bd, 256>>>(Wp, bp, out);
}